// round 1
// baseline (speedup 1.0000x reference)
#include <cuda_runtime.h>

// Problem constants
#define Bb      8
#define Nn      2048
#define Cc      256
#define Ee      32768
#define Hh      8
#define CO      64
#define BN_TOT  (Bb * Nn)          // 16384 nodes
#define F       (Hh * CO)          // 512 features
#define BE      (Bb * Ee)          // 262144 real edges
#define ET      (BE + BN_TOT)      // 278528 edges incl. self loops
#define NEG     0.2f

// ---------------- scratch (static device globals; no allocation) ----------------
__device__ float    g_xt[(size_t)BN_TOT * F];      // projected features, 32 MB
__device__ float    g_asrc[BN_TOT * Hh];           // per-node src attention dot
__device__ float    g_adst[BN_TOT * Hh];           // per-node dst attention dot
__device__ unsigned g_segmax[BN_TOT * Hh];         // encoded float max per (node,head)
__device__ float    g_segsum[BN_TOT * Hh];         // softmax denominator
__device__ float    g_ew[(size_t)ET * Hh];         // logit -> weight -> alpha
__device__ int      g_src[ET];
__device__ int      g_dst[ET];
__device__ int      g_is64;

// ---------------- order-preserving float<->uint encoding for atomicMax ----------
__device__ __forceinline__ unsigned enc_f(float f) {
    unsigned b = __float_as_uint(f);
    return (b & 0x80000000u) ? ~b : (b | 0x80000000u);
}
__device__ __forceinline__ float dec_f(unsigned u) {
    unsigned b = (u & 0x80000000u) ? (u ^ 0x80000000u) : ~u;
    return __uint_as_float(b);
}

// ---------------- edge index dtype detect (int64 vs silently-int32) -------------
__global__ void detect_kernel(const unsigned* __restrict__ w) {
    int lane = threadIdx.x;
    // if edge_index is int64, every odd 32-bit word is a zero high-half
    unsigned v = w[2 * lane + 1];
    unsigned all0 = __all_sync(0xffffffffu, v == 0u);
    if (lane == 0) g_is64 = all0 ? 1 : 0;
}

// ---------------- decode edges into batched int32 src/dst (+ self loops) --------
__global__ void decode_kernel(const void* __restrict__ eiv) {
    int e = blockIdx.x * blockDim.x + threadIdx.x;
    if (e >= ET) return;
    int s, d;
    if (e < BE) {
        int k = e & (Ee - 1);
        int b = e >> 15;             // e / Ee
        if (g_is64) {
            const long long* p = (const long long*)eiv;
            s = (int)p[k];
            d = (int)p[Ee + k];
        } else {
            const int* p = (const int*)eiv;
            s = p[k];
            d = p[Ee + k];
        }
        s += b * Nn;
        d += b * Nn;
    } else {
        s = d = e - BE;              // self loop
    }
    g_src[e] = s;
    g_dst[e] = d;
}

// ---------------- init: out = bias broadcast; zero softmax accumulators ---------
__global__ void init_kernel(float* __restrict__ out, const float* __restrict__ bias) {
    int t = blockIdx.x * blockDim.x + threadIdx.x;
    if (t < BN_TOT * F) out[t] = bias[t & (F - 1)];
    if (t < BN_TOT * Hh) { g_segmax[t] = 0u; g_segsum[t] = 0.0f; }
}

// ---------------- fp32 GEMM: xt[16384,512] = x[16384,256] @ W[256,512] ----------
// 64x64 block tile, BK=16, 256 threads, 4x4 register tile per thread.
__global__ void gemm_kernel(const float* __restrict__ A, const float* __restrict__ Bw) {
    __shared__ float As[16][64];
    __shared__ float Bs[16][64];

    const int tid   = threadIdx.x;
    const int bcol  = blockIdx.x;         // N / 64 = 8
    const int brow  = blockIdx.y;         // M / 64 = 256

    const int arow  = tid >> 2;           // 0..63
    const int acol4 = (tid & 3) << 2;     // 0,4,8,12
    const int brB   = tid >> 4;           // 0..15
    const int bcol4 = (tid & 15) << 2;    // 0..60

    const int tr = (tid >> 4) << 2;       // 0..60 step 4
    const int tc = (tid & 15) << 2;       // 0..60 step 4

    float acc[4][4] = {};

    const float* Aptr = A + (size_t)(brow * 64 + arow) * Cc + acol4;
    const float* Bptr = Bw + (size_t)brB * F + bcol * 64 + bcol4;

    for (int k0 = 0; k0 < Cc; k0 += 16) {
        float4 av = *(const float4*)(Aptr + k0);
        As[acol4 + 0][arow] = av.x;
        As[acol4 + 1][arow] = av.y;
        As[acol4 + 2][arow] = av.z;
        As[acol4 + 3][arow] = av.w;
        *(float4*)&Bs[brB][bcol4] = *(const float4*)(Bptr + (size_t)k0 * F);
        __syncthreads();

#pragma unroll
        for (int k = 0; k < 16; k++) {
            float4 a = *(const float4*)&As[k][tr];
            float4 b = *(const float4*)&Bs[k][tc];
            acc[0][0] += a.x * b.x; acc[0][1] += a.x * b.y; acc[0][2] += a.x * b.z; acc[0][3] += a.x * b.w;
            acc[1][0] += a.y * b.x; acc[1][1] += a.y * b.y; acc[1][2] += a.y * b.z; acc[1][3] += a.y * b.w;
            acc[2][0] += a.z * b.x; acc[2][1] += a.z * b.y; acc[2][2] += a.z * b.z; acc[2][3] += a.z * b.w;
            acc[3][0] += a.w * b.x; acc[3][1] += a.w * b.y; acc[3][2] += a.w * b.z; acc[3][3] += a.w * b.w;
        }
        __syncthreads();
    }

#pragma unroll
    for (int i = 0; i < 4; i++) {
        float4 r = make_float4(acc[i][0], acc[i][1], acc[i][2], acc[i][3]);
        *(float4*)&g_xt[(size_t)(brow * 64 + tr + i) * F + bcol * 64 + tc] = r;
    }
}

// ---------------- per-(node,head) attention dot products (warp each) ------------
__global__ void attdot_kernel(const float* __restrict__ att_src,
                              const float* __restrict__ att_dst) {
    int gw = (blockIdx.x * blockDim.x + threadIdx.x) >> 5;
    int lane = threadIdx.x & 31;
    if (gw >= BN_TOT * Hh) return;
    int n = gw >> 3, h = gw & 7;

    const float* row = g_xt + (size_t)n * F + h * CO;
    float2 v  = *(const float2*)&row[lane * 2];
    float2 as = *(const float2*)&att_src[h * CO + lane * 2];
    float2 ad = *(const float2*)&att_dst[h * CO + lane * 2];
    float s = v.x * as.x + v.y * as.y;
    float d = v.x * ad.x + v.y * ad.y;
#pragma unroll
    for (int o = 16; o; o >>= 1) {
        s += __shfl_xor_sync(0xffffffffu, s, o);
        d += __shfl_xor_sync(0xffffffffu, d, o);
    }
    if (lane == 0) { g_asrc[gw] = s; g_adst[gw] = d; }
}

// ---------------- pass A: logits + segment max ----------------------------------
__global__ void logit_kernel() {
    int t = blockIdx.x * blockDim.x + threadIdx.x;
    if (t >= ET * Hh) return;
    int e = t >> 3, h = t & 7;
    int src = g_src[e], dst = g_dst[e];
    float l = g_asrc[src * Hh + h] + g_adst[dst * Hh + h];
    l = (l > 0.0f) ? l : NEG * l;
    g_ew[t] = l;
    atomicMax(&g_segmax[dst * Hh + h], enc_f(l));
}

// ---------------- pass B: exp(l - max) + segment sum ----------------------------
__global__ void exp_kernel() {
    int t = blockIdx.x * blockDim.x + threadIdx.x;
    if (t >= ET * Hh) return;
    int e = t >> 3, h = t & 7;
    int dst = g_dst[e];
    float m = dec_f(g_segmax[dst * Hh + h]);
    float w = expf(g_ew[t] - m);
    g_ew[t] = w;
    atomicAdd(&g_segsum[dst * Hh + h], w);
}

// ---------------- pass B2: normalize --------------------------------------------
__global__ void alpha_kernel() {
    int t = blockIdx.x * blockDim.x + threadIdx.x;
    if (t >= ET * Hh) return;
    int e = t >> 3;
    int h = t & 7;
    int dst = g_dst[e];
    g_ew[t] = g_ew[t] / (g_segsum[dst * Hh + h] + 1e-16f);
}

// ---------------- pass C: weighted scatter-add (vector RED) ---------------------
// 16 threads per (edge,head); each does one float4 load + one float4 atomicAdd.
__global__ void scatter_kernel(float* __restrict__ out) {
    int t = blockIdx.x * blockDim.x + threadIdx.x;
    if (t >= ET * Hh * 16) return;
    int q = t & 15;
    int g = t >> 4;
    int h = g & 7;
    int e = g >> 3;
    float a = g_ew[g];
    int src = g_src[e], dst = g_dst[e];
    float4 v = *(const float4*)&g_xt[(size_t)src * F + h * CO + q * 4];
    float4 m = make_float4(v.x * a, v.y * a, v.z * a, v.w * a);
    atomicAdd((float4*)&out[(size_t)dst * F + h * CO + q * 4], m);  // -> RED.E.ADD.128
}

// ---------------- launch --------------------------------------------------------
extern "C" void kernel_launch(void* const* d_in, const int* in_sizes, int n_in,
                              void* d_out, int out_size) {
    const float* x    = (const float*)d_in[0];
    const void*  ei   = d_in[1];
    const float* W    = (const float*)d_in[2];
    const float* asrc = (const float*)d_in[3];
    const float* adst = (const float*)d_in[4];
    const float* bias = (const float*)d_in[5];
    float* out = (float*)d_out;

    detect_kernel<<<1, 32>>>((const unsigned*)ei);
    decode_kernel<<<(ET + 255) / 256, 256>>>(ei);
    init_kernel<<<(BN_TOT * F + 255) / 256, 256>>>(out, bias);
    gemm_kernel<<<dim3(F / 64, BN_TOT / 64), 256>>>(x, W);
    attdot_kernel<<<(BN_TOT * Hh * 32 + 255) / 256, 256>>>(asrc, adst);

    int et_h = ET * Hh;
    logit_kernel<<<(et_h + 255) / 256, 256>>>();
    exp_kernel<<<(et_h + 255) / 256, 256>>>();
    alpha_kernel<<<(et_h + 255) / 256, 256>>>();
    scatter_kernel<<<(et_h * 16 + 255) / 256, 256>>>(out);
}

// round 2
// speedup vs baseline: 1.1962x; 1.1962x over previous
#include <cuda_runtime.h>
#include <math.h>

// Problem constants
#define Bb      8
#define Nn      2048
#define Cc      256
#define Ee      32768
#define Hh      8
#define CO      64
#define BN_TOT  (Bb * Nn)          // 16384 nodes
#define F       (Hh * CO)          // 512 features
#define BE      (Bb * Ee)          // 262144 real edges
#define ET      (BE + BN_TOT)      // 278528 edges incl. self loops
#define NEG     0.2f

// ---------------- scratch (static device globals; no allocation) ----------------
__device__ float g_xt[(size_t)BN_TOT * F];     // projected features, 32 MB
__device__ float g_asrc[BN_TOT * Hh];          // per-node src attention dot
__device__ float g_adst[BN_TOT * Hh];          // per-node dst attention dot
__device__ int   g_src[ET];
__device__ int   g_dst[ET];
__device__ int   g_cnt[BN_TOT];                // in-degree counts
__device__ int   g_rowptr[BN_TOT + 1];         // CSR row pointers (by dst)
__device__ int   g_ofs[BN_TOT];                // running offsets for place
__device__ int   g_csrc[ET];                   // CSR: src node per slot
__device__ int   g_is64;

// ---------------- edge index dtype detect (int64 vs silently-int32) -------------
__global__ void detect_kernel(const unsigned* __restrict__ w) {
    int lane = threadIdx.x;
    unsigned v = w[2 * lane + 1];          // int64 => odd words are zero high-halves
    unsigned all0 = __all_sync(0xffffffffu, v == 0u);
    if (lane == 0) g_is64 = all0 ? 1 : 0;
}

__global__ void zero_cnt_kernel() {
    int t = blockIdx.x * blockDim.x + threadIdx.x;
    if (t < BN_TOT) g_cnt[t] = 0;
}

// ---------------- decode batched edges (+ self loops) and count in-degrees ------
__global__ void decode_count_kernel(const void* __restrict__ eiv) {
    int e = blockIdx.x * blockDim.x + threadIdx.x;
    if (e >= ET) return;
    int s, d;
    if (e < BE) {
        int k = e & (Ee - 1);
        int b = e >> 15;                   // e / Ee
        if (g_is64) {
            const long long* p = (const long long*)eiv;
            s = (int)p[k];
            d = (int)p[Ee + k];
        } else {
            const int* p = (const int*)eiv;
            s = p[k];
            d = p[Ee + k];
        }
        s += b * Nn;
        d += b * Nn;
    } else {
        s = d = e - BE;                    // self loop
    }
    g_src[e] = s;
    g_dst[e] = d;
    atomicAdd(&g_cnt[d], 1);
}

// ---------------- single-block exclusive scan over 16384 counts -----------------
__global__ void scan_kernel() {
    __shared__ int sh[1024];
    int t = threadIdx.x;
    int base = t * 16;
    int loc[16];
    int s = 0;
#pragma unroll
    for (int i = 0; i < 16; i++) { loc[i] = s; s += g_cnt[base + i]; }
    sh[t] = s;
    __syncthreads();
    for (int off = 1; off < 1024; off <<= 1) {
        int v = (t >= off) ? sh[t - off] : 0;
        __syncthreads();
        sh[t] += v;
        __syncthreads();
    }
    int pre = (t == 0) ? 0 : sh[t - 1];
#pragma unroll
    for (int i = 0; i < 16; i++) {
        int r = pre + loc[i];
        g_rowptr[base + i] = r;
        g_ofs[base + i] = r;
    }
    if (t == 1023) g_rowptr[BN_TOT] = sh[1023];
}

// ---------------- place edges into CSR slots ------------------------------------
__global__ void place_kernel() {
    int e = blockIdx.x * blockDim.x + threadIdx.x;
    if (e >= ET) return;
    int d = g_dst[e];
    int slot = atomicAdd(&g_ofs[d], 1);
    g_csrc[slot] = g_src[e];
}

// ---------------- fp32 GEMM: xt[16384,512] = x[16384,256] @ W[256,512] ----------
// 128x128 block tile, BK=16, 256 threads, 8x8 register tile per thread.
#define TM 128
#define TN 128
#define BK 16
__global__ void gemm_kernel(const float* __restrict__ A, const float* __restrict__ Bw) {
    __shared__ float As[BK][TM];
    __shared__ float Bs[BK][TN];

    const int tid = threadIdx.x;
    const int bx  = blockIdx.x;            // N / 128 = 4
    const int by  = blockIdx.y;            // M / 128 = 128

    const int tr = (tid >> 4) << 3;        // 0..120 step 8
    const int tc = (tid & 15) << 3;        // 0..120 step 8

    // A tile loaders: rows ar and ar+64, cols ak..ak+3
    const int ar = tid >> 2;               // 0..63
    const int ak = (tid & 3) << 2;         // 0,4,8,12
    // B tile loaders: rows br and br+8, cols bc..bc+3
    const int br = tid >> 5;               // 0..7
    const int bc = (tid & 31) << 2;        // 0..124

    float acc[8][8] = {};

    const float* Ap = A + (size_t)(by * TM + ar) * Cc + ak;
    const float* Bp = Bw + (size_t)br * F + bx * TN + bc;

    for (int k0 = 0; k0 < Cc; k0 += BK) {
        float4 a0 = *(const float4*)(Ap + k0);
        float4 a1 = *(const float4*)(Ap + (size_t)64 * Cc + k0);
        As[ak + 0][ar] = a0.x; As[ak + 1][ar] = a0.y;
        As[ak + 2][ar] = a0.z; As[ak + 3][ar] = a0.w;
        As[ak + 0][ar + 64] = a1.x; As[ak + 1][ar + 64] = a1.y;
        As[ak + 2][ar + 64] = a1.z; As[ak + 3][ar + 64] = a1.w;
        *(float4*)&Bs[br][bc]     = *(const float4*)(Bp + (size_t)k0 * F);
        *(float4*)&Bs[br + 8][bc] = *(const float4*)(Bp + (size_t)(k0 + 8) * F);
        __syncthreads();

#pragma unroll
        for (int k = 0; k < BK; k++) {
            float4 x0 = *(const float4*)&As[k][tr];
            float4 x1 = *(const float4*)&As[k][tr + 4];
            float4 y0 = *(const float4*)&Bs[k][tc];
            float4 y1 = *(const float4*)&Bs[k][tc + 4];
            float av[8] = {x0.x, x0.y, x0.z, x0.w, x1.x, x1.y, x1.z, x1.w};
            float bv[8] = {y0.x, y0.y, y0.z, y0.w, y1.x, y1.y, y1.z, y1.w};
#pragma unroll
            for (int i = 0; i < 8; i++)
#pragma unroll
                for (int j = 0; j < 8; j++)
                    acc[i][j] += av[i] * bv[j];
        }
        __syncthreads();
    }

#pragma unroll
    for (int i = 0; i < 8; i++) {
        size_t row = (size_t)(by * TM + tr + i);
        float* o = g_xt + row * F + bx * TN + tc;
        *(float4*)(o)     = make_float4(acc[i][0], acc[i][1], acc[i][2], acc[i][3]);
        *(float4*)(o + 4) = make_float4(acc[i][4], acc[i][5], acc[i][6], acc[i][7]);
    }
}

// ---------------- per-(node,head) attention dot products (warp each) ------------
__global__ void attdot_kernel(const float* __restrict__ att_src,
                              const float* __restrict__ att_dst) {
    int gw = (blockIdx.x * blockDim.x + threadIdx.x) >> 5;
    int lane = threadIdx.x & 31;
    if (gw >= BN_TOT * Hh) return;
    int n = gw >> 3, h = gw & 7;

    const float* row = g_xt + (size_t)n * F + h * CO;
    float2 v  = *(const float2*)&row[lane * 2];
    float2 as = *(const float2*)&att_src[h * CO + lane * 2];
    float2 ad = *(const float2*)&att_dst[h * CO + lane * 2];
    float s = v.x * as.x + v.y * as.y;
    float d = v.x * ad.x + v.y * ad.y;
#pragma unroll
    for (int o = 16; o; o >>= 1) {
        s += __shfl_xor_sync(0xffffffffu, s, o);
        d += __shfl_xor_sync(0xffffffffu, d, o);
    }
    if (lane == 0) { g_asrc[gw] = s; g_adst[gw] = d; }
}

// ---------------- fused softmax + weighted gather (no atomics) ------------------
// One block per dst node; one warp per head; lane covers 2 channels.
__global__ void gather_kernel(float* __restrict__ out, const float* __restrict__ bias) {
    int n = blockIdx.x;
    int h = threadIdx.x >> 5;
    int lane = threadIdx.x & 31;
    int start = g_rowptr[n];
    int end   = g_rowptr[n + 1];

    float adstv = g_adst[n * Hh + h];

    // pass 1: segment max
    float m = -1e30f;
    for (int i = start + lane; i < end; i += 32) {
        int s = g_csrc[i];
        float l = g_asrc[s * Hh + h] + adstv;
        l = (l > 0.0f) ? l : NEG * l;
        m = fmaxf(m, l);
    }
#pragma unroll
    for (int o = 16; o; o >>= 1) m = fmaxf(m, __shfl_xor_sync(0xffffffffu, m, o));

    // pass 2: sum of exp(l - m)
    float sum = 0.0f;
    for (int i = start + lane; i < end; i += 32) {
        int s = g_csrc[i];
        float l = g_asrc[s * Hh + h] + adstv;
        l = (l > 0.0f) ? l : NEG * l;
        sum += expf(l - m);
    }
#pragma unroll
    for (int o = 16; o; o >>= 1) sum += __shfl_xor_sync(0xffffffffu, sum, o);
    float inv = 1.0f / (sum + 1e-16f);

    // pass 3: weighted feature accumulation (alpha recomputed; loads broadcast)
    float2 acc = make_float2(0.0f, 0.0f);
    const float* xb = g_xt + h * CO + lane * 2;
    for (int i = start; i < end; i++) {
        int s = g_csrc[i];
        float l = g_asrc[s * Hh + h] + adstv;
        l = (l > 0.0f) ? l : NEG * l;
        float a = expf(l - m) * inv;
        float2 v = *(const float2*)(xb + (size_t)s * F);
        acc.x += a * v.x;
        acc.y += a * v.y;
    }

    int c = h * CO + lane * 2;
    float2 bv = *(const float2*)(bias + c);
    *(float2*)(out + (size_t)n * F + c) = make_float2(acc.x + bv.x, acc.y + bv.y);
}

// ---------------- launch --------------------------------------------------------
extern "C" void kernel_launch(void* const* d_in, const int* in_sizes, int n_in,
                              void* d_out, int out_size) {
    const float* x    = (const float*)d_in[0];
    const void*  ei   = d_in[1];
    const float* W    = (const float*)d_in[2];
    const float* asrc = (const float*)d_in[3];
    const float* adst = (const float*)d_in[4];
    const float* bias = (const float*)d_in[5];
    float* out = (float*)d_out;

    detect_kernel<<<1, 32>>>((const unsigned*)ei);
    zero_cnt_kernel<<<(BN_TOT + 255) / 256, 256>>>();
    decode_count_kernel<<<(ET + 255) / 256, 256>>>(ei);
    scan_kernel<<<1, 1024>>>();
    place_kernel<<<(ET + 255) / 256, 256>>>();

    gemm_kernel<<<dim3(F / TN, BN_TOT / TM), 256>>>(x, W);
    attdot_kernel<<<(BN_TOT * Hh * 32 + 255) / 256, 256>>>(asrc, adst);
    gather_kernel<<<BN_TOT, 256>>>(out, bias);
}

// round 3
// speedup vs baseline: 1.5372x; 1.2850x over previous
#include <cuda_runtime.h>
#include <math.h>

// Problem constants
#define Bb      8
#define Nn      2048
#define Cc      256
#define Ee      32768
#define Hh      8
#define CO      64
#define BN_TOT  (Bb * Nn)          // 16384 nodes
#define F       (Hh * CO)          // 512 features
#define BE      (Bb * Ee)          // 262144 real edges
#define ET      (BE + BN_TOT)      // 278528 edges incl. self loops
#define NEG     0.2f

// ---------------- scratch (static device globals; no allocation) ----------------
__device__ float g_xt[(size_t)BN_TOT * F];     // projected features, 32 MB
__device__ float g_asrc[BN_TOT * Hh];          // per-node src attention dot
__device__ float g_adst[BN_TOT * Hh];          // per-node dst attention dot
__device__ int   g_src[ET];
__device__ int   g_dst[ET];
__device__ int   g_cnt[BN_TOT];                // in-degree counts
__device__ int   g_rowptr[BN_TOT + 1];         // CSR row pointers (by dst)
__device__ int   g_ofs[BN_TOT];                // running offsets for place
__device__ int   g_csrc[ET];                   // CSR: src node per slot
__device__ int   g_is64;

// ---------------- detect edge dtype + zero counts (merged) ----------------------
__global__ void detect_zero_kernel(const unsigned* __restrict__ w) {
    int t = blockIdx.x * blockDim.x + threadIdx.x;
    if (t < BN_TOT) g_cnt[t] = 0;
    if (blockIdx.x == 0 && threadIdx.x < 32) {
        // if edge_index is int64, every odd 32-bit word is a zero high-half
        unsigned v = w[2 * threadIdx.x + 1];
        unsigned all0 = __all_sync(0xffffffffu, v == 0u);
        if (threadIdx.x == 0) g_is64 = all0 ? 1 : 0;
    }
}

// ---------------- decode batched edges (+ self loops) and count in-degrees ------
__global__ void decode_count_kernel(const void* __restrict__ eiv) {
    int e = blockIdx.x * blockDim.x + threadIdx.x;
    if (e >= ET) return;
    int s, d;
    if (e < BE) {
        int k = e & (Ee - 1);
        int b = e >> 15;                   // e / Ee
        if (g_is64) {
            const long long* p = (const long long*)eiv;
            s = (int)p[k];
            d = (int)p[Ee + k];
        } else {
            const int* p = (const int*)eiv;
            s = p[k];
            d = p[Ee + k];
        }
        s += b * Nn;
        d += b * Nn;
    } else {
        s = d = e - BE;                    // self loop
    }
    g_src[e] = s;
    g_dst[e] = d;
    atomicAdd(&g_cnt[d], 1);
}

// ---------------- single-block exclusive scan over 16384 counts -----------------
// 1024 threads x 16 elements. int4 loads, local prefix, warp-shuffle scan,
// warp-total scan. No serial global-load chains, 2 barriers total.
__global__ void scan_kernel() {
    __shared__ int wsum[32];
    const int t = threadIdx.x;
    const int lane = t & 31;
    const int w = t >> 5;

    const int4* cin = (const int4*)g_cnt;
    int4 c0 = cin[t * 4 + 0];
    int4 c1 = cin[t * 4 + 1];
    int4 c2 = cin[t * 4 + 2];
    int4 c3 = cin[t * 4 + 3];
    int v[16] = {c0.x, c0.y, c0.z, c0.w, c1.x, c1.y, c1.z, c1.w,
                 c2.x, c2.y, c2.z, c2.w, c3.x, c3.y, c3.z, c3.w};

    int loc[16];
    int s = 0;
#pragma unroll
    for (int i = 0; i < 16; i++) { loc[i] = s; s += v[i]; }

    // warp inclusive scan of per-thread totals
    int inc = s;
#pragma unroll
    for (int o = 1; o < 32; o <<= 1) {
        int u = __shfl_up_sync(0xffffffffu, inc, o);
        if (lane >= o) inc += u;
    }
    if (lane == 31) wsum[w] = inc;
    __syncthreads();
    if (w == 0) {
        int x = wsum[lane];
#pragma unroll
        for (int o = 1; o < 32; o <<= 1) {
            int u = __shfl_up_sync(0xffffffffu, x, o);
            if (lane >= o) x += u;
        }
        wsum[lane] = x;   // inclusive warp totals
    }
    __syncthreads();

    int base_excl = (inc - s) + (w > 0 ? wsum[w - 1] : 0);

    int r[16];
#pragma unroll
    for (int i = 0; i < 16; i++) r[i] = base_excl + loc[i];

    int4* rp = (int4*)g_rowptr;     // g_rowptr[0..16383] is 16-byte aligned region
    int4* op = (int4*)g_ofs;
#pragma unroll
    for (int i = 0; i < 4; i++) {
        int4 q = make_int4(r[i * 4 + 0], r[i * 4 + 1], r[i * 4 + 2], r[i * 4 + 3]);
        rp[t * 4 + i] = q;
        op[t * 4 + i] = q;
    }
    if (t == 1023) g_rowptr[BN_TOT] = wsum[31];
}

// ---------------- place edges into CSR slots ------------------------------------
__global__ void place_kernel() {
    int e = blockIdx.x * blockDim.x + threadIdx.x;
    if (e >= ET) return;
    int d = g_dst[e];
    int slot = atomicAdd(&g_ofs[d], 1);
    g_csrc[slot] = g_src[e];
}

// ---------------- fp32 GEMM: xt[16384,512] = x[16384,256] @ W[256,512] ----------
// 128x128 block tile, BK=16, 256 threads, 8x8 register tile per thread.
#define TM 128
#define TN 128
#define BK 16
__global__ void gemm_kernel(const float* __restrict__ A, const float* __restrict__ Bw) {
    __shared__ float As[BK][TM];
    __shared__ float Bs[BK][TN];

    const int tid = threadIdx.x;
    const int bx  = blockIdx.x;            // N / 128 = 4
    const int by  = blockIdx.y;            // M / 128 = 128

    const int tr = (tid >> 4) << 3;        // 0..120 step 8
    const int tc = (tid & 15) << 3;        // 0..120 step 8

    const int ar = tid >> 2;               // 0..63
    const int ak = (tid & 3) << 2;         // 0,4,8,12
    const int br = tid >> 5;               // 0..7
    const int bc = (tid & 31) << 2;        // 0..124

    float acc[8][8] = {};

    const float* Ap = A + (size_t)(by * TM + ar) * Cc + ak;
    const float* Bp = Bw + (size_t)br * F + bx * TN + bc;

    for (int k0 = 0; k0 < Cc; k0 += BK) {
        float4 a0 = *(const float4*)(Ap + k0);
        float4 a1 = *(const float4*)(Ap + (size_t)64 * Cc + k0);
        As[ak + 0][ar] = a0.x; As[ak + 1][ar] = a0.y;
        As[ak + 2][ar] = a0.z; As[ak + 3][ar] = a0.w;
        As[ak + 0][ar + 64] = a1.x; As[ak + 1][ar + 64] = a1.y;
        As[ak + 2][ar + 64] = a1.z; As[ak + 3][ar + 64] = a1.w;
        *(float4*)&Bs[br][bc]     = *(const float4*)(Bp + (size_t)k0 * F);
        *(float4*)&Bs[br + 8][bc] = *(const float4*)(Bp + (size_t)(k0 + 8) * F);
        __syncthreads();

#pragma unroll
        for (int k = 0; k < BK; k++) {
            float4 x0 = *(const float4*)&As[k][tr];
            float4 x1 = *(const float4*)&As[k][tr + 4];
            float4 y0 = *(const float4*)&Bs[k][tc];
            float4 y1 = *(const float4*)&Bs[k][tc + 4];
            float av[8] = {x0.x, x0.y, x0.z, x0.w, x1.x, x1.y, x1.z, x1.w};
            float bv[8] = {y0.x, y0.y, y0.z, y0.w, y1.x, y1.y, y1.z, y1.w};
#pragma unroll
            for (int i = 0; i < 8; i++)
#pragma unroll
                for (int j = 0; j < 8; j++)
                    acc[i][j] += av[i] * bv[j];
        }
        __syncthreads();
    }

#pragma unroll
    for (int i = 0; i < 8; i++) {
        size_t row = (size_t)(by * TM + tr + i);
        float* o = g_xt + row * F + bx * TN + tc;
        *(float4*)(o)     = make_float4(acc[i][0], acc[i][1], acc[i][2], acc[i][3]);
        *(float4*)(o + 4) = make_float4(acc[i][4], acc[i][5], acc[i][6], acc[i][7]);
    }
}

// ---------------- per-(node,head) attention dot products (warp each) ------------
__global__ void attdot_kernel(const float* __restrict__ att_src,
                              const float* __restrict__ att_dst) {
    int gw = (blockIdx.x * blockDim.x + threadIdx.x) >> 5;
    int lane = threadIdx.x & 31;
    if (gw >= BN_TOT * Hh) return;
    int n = gw >> 3, h = gw & 7;

    const float* row = g_xt + (size_t)n * F + h * CO;
    float2 v  = *(const float2*)&row[lane * 2];
    float2 as = *(const float2*)&att_src[h * CO + lane * 2];
    float2 ad = *(const float2*)&att_dst[h * CO + lane * 2];
    float s = v.x * as.x + v.y * as.y;
    float d = v.x * ad.x + v.y * ad.y;
#pragma unroll
    for (int o = 16; o; o >>= 1) {
        s += __shfl_xor_sync(0xffffffffu, s, o);
        d += __shfl_xor_sync(0xffffffffu, d, o);
    }
    if (lane == 0) { g_asrc[gw] = s; g_adst[gw] = d; }
}

// ---------------- fused softmax + weighted gather (no atomics) ------------------
// One block per dst node; one warp per head; lane covers 2 channels.
// Pass 3 uses shuffle-broadcast of per-lane alpha: inner loop is
// 2 SHFL + 1 coalesced 256B load + 2 FFMA per edge.
__global__ void gather_kernel(float* __restrict__ out, const float* __restrict__ bias) {
    int n = blockIdx.x;
    int h = threadIdx.x >> 5;
    int lane = threadIdx.x & 31;
    int start = g_rowptr[n];
    int end   = g_rowptr[n + 1];

    float adstv = g_adst[n * Hh + h];

    // pass 1: segment max
    float m = -1e30f;
    for (int i = start + lane; i < end; i += 32) {
        int s = g_csrc[i];
        float l = g_asrc[s * Hh + h] + adstv;
        l = (l > 0.0f) ? l : NEG * l;
        m = fmaxf(m, l);
    }
#pragma unroll
    for (int o = 16; o; o >>= 1) m = fmaxf(m, __shfl_xor_sync(0xffffffffu, m, o));

    // pass 2: sum of exp(l - m)
    float sum = 0.0f;
    for (int i = start + lane; i < end; i += 32) {
        int s = g_csrc[i];
        float l = g_asrc[s * Hh + h] + adstv;
        l = (l > 0.0f) ? l : NEG * l;
        sum += expf(l - m);
    }
#pragma unroll
    for (int o = 16; o; o >>= 1) sum += __shfl_xor_sync(0xffffffffu, sum, o);
    float inv = 1.0f / (sum + 1e-16f);

    // pass 3: chunked weighted feature accumulation with shuffle broadcast
    float2 acc = make_float2(0.0f, 0.0f);
    const float* xb = g_xt + h * CO + lane * 2;
    for (int base = start; base < end; base += 32) {
        int i = base + lane;
        int sreg = 0;
        float areg = 0.0f;
        if (i < end) {
            sreg = g_csrc[i];
            float l = g_asrc[sreg * Hh + h] + adstv;
            l = (l > 0.0f) ? l : NEG * l;
            areg = expf(l - m) * inv;
        }
        int cnt = end - base;
        if (cnt > 32) cnt = 32;
        for (int j = 0; j < cnt; j++) {
            float a = __shfl_sync(0xffffffffu, areg, j);
            int   s = __shfl_sync(0xffffffffu, sreg, j);
            float2 v = *(const float2*)(xb + (size_t)s * F);
            acc.x += a * v.x;
            acc.y += a * v.y;
        }
    }

    int c = h * CO + lane * 2;
    float2 bv = *(const float2*)(bias + c);
    *(float2*)(out + (size_t)n * F + c) = make_float2(acc.x + bv.x, acc.y + bv.y);
}

// ---------------- launch (fork-join: CSR build || GEMM+attdot) ------------------
extern "C" void kernel_launch(void* const* d_in, const int* in_sizes, int n_in,
                              void* d_out, int out_size) {
    const float* x    = (const float*)d_in[0];
    const void*  ei   = d_in[1];
    const float* W    = (const float*)d_in[2];
    const float* asrc = (const float*)d_in[3];
    const float* adst = (const float*)d_in[4];
    const float* bias = (const float*)d_in[5];
    float* out = (float*)d_out;

    static cudaStream_t s2 = nullptr;
    static cudaEvent_t ev_fork = nullptr, ev_join = nullptr;
    if (s2 == nullptr) {
        cudaStreamCreateWithFlags(&s2, cudaStreamNonBlocking);
        cudaEventCreateWithFlags(&ev_fork, cudaEventDisableTiming);
        cudaEventCreateWithFlags(&ev_join, cudaEventDisableTiming);
    }

    // fork: GEMM branch on s2, CSR build on the main (capture) stream
    cudaEventRecord(ev_fork, 0);
    cudaStreamWaitEvent(s2, ev_fork, 0);

    gemm_kernel<<<dim3(F / TN, BN_TOT / TM), 256, 0, s2>>>(x, W);
    attdot_kernel<<<(BN_TOT * Hh * 32 + 255) / 256, 256, 0, s2>>>(asrc, adst);
    cudaEventRecord(ev_join, s2);

    detect_zero_kernel<<<BN_TOT / 256, 256>>>((const unsigned*)ei);
    decode_count_kernel<<<(ET + 255) / 256, 256>>>(ei);
    scan_kernel<<<1, 1024>>>();
    place_kernel<<<(ET + 255) / 256, 256>>>();

    // join, then gather needs both branches
    cudaStreamWaitEvent(0, ev_join, 0);
    gather_kernel<<<BN_TOT, 256>>>(out, bias);
}